// round 4
// baseline (speedup 1.0000x reference)
#include <cuda_runtime.h>

#define DD 4096

typedef unsigned long long u64;

__device__ float g_dev[DD];

__global__ void compute_g_kernel(const float* __restrict__ eps,
                                 const float* __restrict__ g_mu,
                                 const float* __restrict__ g_rho) {
    int i = blockIdx.x * blockDim.x + threadIdx.x;
    if (i < DD) {
        float r = g_rho[i];
        g_dev[i] = g_mu[i] + log1pf(expf(r)) * eps[i];
    }
}

__device__ __forceinline__ u64 ADD2(u64 a, u64 b){ u64 c; asm("add.rn.f32x2 %0, %1, %2;" : "=l"(c) : "l"(a), "l"(b)); return c; }
__device__ __forceinline__ u64 SUB2(u64 a, u64 b){ u64 c; asm("sub.rn.f32x2 %0, %1, %2;" : "=l"(c) : "l"(a), "l"(b)); return c; }
__device__ __forceinline__ u64 MUL2(u64 a, u64 b){ u64 c; asm("mul.rn.f32x2 %0, %1, %2;" : "=l"(c) : "l"(a), "l"(b)); return c; }
__device__ __forceinline__ u64 PACK2(float lo, float hi){ u64 c; asm("mov.b64 %0, {%1, %2};" : "=l"(c) : "f"(lo), "f"(hi)); return c; }
__device__ __forceinline__ float2 UNPK(u64 v){ float2 r; asm("mov.b64 {%0, %1}, %2;" : "=f"(r.x), "=f"(r.y) : "l"(v)); return r; }

// Same bank swizzle as the proven R3 kernel: phys(i) = i ^ (((i>>5)^(i>>10))&31).
// Conflict-free for all three phase layouts below (32-bit accesses).
__device__ __forceinline__ int PHYS(int i) {
    return i ^ (((i >> 5) ^ (i >> 10)) & 31);
}

// Radix-16 FWHT over the register index; each u64 packs (rowA[i], rowB[i]),
// so every butterfly is one packed f32x2 instruction serving two rows.
__device__ __forceinline__ void fwht16(u64 v[16]) {
#pragma unroll
    for (int s = 0; s < 4; s++) {
        const int h = 1 << s;
#pragma unroll
        for (int q = 0; q < 16; q += 2*h) {
#pragma unroll
            for (int j = 0; j < h; j++) {
                u64 a = v[q+j], b = v[q+j+h];
                v[q+j]   = ADD2(a, b);
                v[q+j+h] = SUB2(a, b);
            }
        }
    }
}

// y_row = s1 * FWHT( g * FWHT( s2 * x_row ) ),  FWHT_4096 = F_A . F_B . F_C.
//   Phase A: regs = bits {0..3},  lanes = bits {4..8},  warps = bits {9..11}
//   Phase B: regs = bits {4..7},  lanes = bits {0,1,2,8,9}, warps = {3,10,11}
//   Phase C: regs = bits {8..11}, lanes = bits {0..4},  warps = bits {5..7}
// Two rows per CTA, packed in f32x2 registers. Shared memory is two scalar
// 32-bit planes (rowA at sm[idx], rowB at sm[idx+DD]) so the R3 conflict-free
// swizzle applies unchanged and both STS/LDS of a pair share one address.
__global__ void __launch_bounds__(256, 4)
whvi_kernel(const float* __restrict__ x,
            const float* __restrict__ s1,
            const float* __restrict__ s2,
            float* __restrict__ out) {
    __shared__ float sm[2 * DD];

    const int t = threadIdx.x;
    const int l = t & 31;
    const int w = t >> 5;

    const int baseA = 16*l + 512*w;
    const int baseB = (l & 7) + 8*(w & 1) + 256*(l >> 3) + 1024*(w >> 1);
    const int baseC = l + 32*w;
    const int pA = PHYS(baseA);
    const int pB = PHYS(baseB);
    const int pC = PHYS(baseC);

    const long long rowA = 2LL * blockIdx.x;
    const float* xa = x + rowA * DD;
    const float* xb = xa + DD;

    u64 v[16];

    // ---- P1: coalesced load both rows, *s2, F_A ----
#pragma unroll
    for (int q = 0; q < 4; q++) {
        float4 a = *reinterpret_cast<const float4*>(xa + baseA + 4*q);
        float4 b = *reinterpret_cast<const float4*>(xb + baseA + 4*q);
        float4 s = *reinterpret_cast<const float4*>(s2 + baseA + 4*q);
        v[4*q+0] = PACK2(a.x*s.x, b.x*s.x);
        v[4*q+1] = PACK2(a.y*s.y, b.y*s.y);
        v[4*q+2] = PACK2(a.z*s.z, b.z*s.z);
        v[4*q+3] = PACK2(a.w*s.w, b.w*s.w);
    }
    fwht16(v);
#pragma unroll
    for (int r = 0; r < 16; r++) {
        const int i = pA ^ PHYS(r);
        float2 p = UNPK(v[r]);
        sm[i] = p.x;
        sm[i + DD] = p.y;
    }
    __syncthreads();

    // ---- P2: F_B ----
#pragma unroll
    for (int r = 0; r < 16; r++) {
        const int i = pB ^ PHYS(16*r);
        v[r] = PACK2(sm[i], sm[i + DD]);
    }
    fwht16(v);
#pragma unroll
    for (int r = 0; r < 16; r++) {
        const int i = pB ^ PHYS(16*r);
        float2 p = UNPK(v[r]);
        sm[i] = p.x;
        sm[i + DD] = p.y;
    }
    __syncthreads();

    // ---- P3: F_C, *g, F_C ----
#pragma unroll
    for (int r = 0; r < 16; r++) {
        const int i = pC ^ PHYS(256*r);
        v[r] = PACK2(sm[i], sm[i + DD]);
    }
    fwht16(v);
#pragma unroll
    for (int r = 0; r < 16; r++) {
        const float gv = g_dev[baseC + 256*r];
        v[r] = MUL2(v[r], PACK2(gv, gv));
    }
    fwht16(v);
#pragma unroll
    for (int r = 0; r < 16; r++) {
        const int i = pC ^ PHYS(256*r);
        float2 p = UNPK(v[r]);
        sm[i] = p.x;
        sm[i + DD] = p.y;
    }
    __syncthreads();

    // ---- P4: F_B ----
#pragma unroll
    for (int r = 0; r < 16; r++) {
        const int i = pB ^ PHYS(16*r);
        v[r] = PACK2(sm[i], sm[i + DD]);
    }
    fwht16(v);
#pragma unroll
    for (int r = 0; r < 16; r++) {
        const int i = pB ^ PHYS(16*r);
        float2 p = UNPK(v[r]);
        sm[i] = p.x;
        sm[i + DD] = p.y;
    }
    __syncthreads();

    // ---- P5: F_A, *s1, coalesced store both rows ----
#pragma unroll
    for (int r = 0; r < 16; r++) {
        const int i = pA ^ PHYS(r);
        v[r] = PACK2(sm[i], sm[i + DD]);
    }
    fwht16(v);

    float* oa = out + rowA * DD;
    float* ob = oa + DD;
#pragma unroll
    for (int q = 0; q < 4; q++) {
        float4 s = *reinterpret_cast<const float4*>(s1 + baseA + 4*q);
        float2 p0 = UNPK(MUL2(v[4*q+0], PACK2(s.x, s.x)));
        float2 p1 = UNPK(MUL2(v[4*q+1], PACK2(s.y, s.y)));
        float2 p2 = UNPK(MUL2(v[4*q+2], PACK2(s.z, s.z)));
        float2 p3 = UNPK(MUL2(v[4*q+3], PACK2(s.w, s.w)));
        *reinterpret_cast<float4*>(oa + baseA + 4*q) = make_float4(p0.x, p1.x, p2.x, p3.x);
        *reinterpret_cast<float4*>(ob + baseA + 4*q) = make_float4(p0.y, p1.y, p2.y, p3.y);
    }
}

extern "C" void kernel_launch(void* const* d_in, const int* in_sizes, int n_in,
                              void* d_out, int out_size) {
    const float* x     = (const float*)d_in[0];
    const float* eps   = (const float*)d_in[1];
    const float* s1    = (const float*)d_in[2];
    const float* s2    = (const float*)d_in[3];
    const float* g_mu  = (const float*)d_in[4];
    const float* g_rho = (const float*)d_in[5];
    float* out = (float*)d_out;

    int B = in_sizes[0] / DD;   // 2048

    compute_g_kernel<<<(DD + 255) / 256, 256>>>(eps, g_mu, g_rho);
    whvi_kernel<<<B / 2, 256>>>(x, s1, s2, out);
}